// round 13
// baseline (speedup 1.0000x reference)
#include <cuda_runtime.h>
#include <math.h>

#define D_    1024
#define E_    8
#define B_    64
#define S_    1024
#define NTOK  65536
#define NB2   512                  // K2 blocks: 128 tokens each (8 blocks/batch)
#define MASK_N   (B_*S_*E_)        // 524288
#define IDX_OFF  MASK_N
#define LOSS_OFF (MASK_N + B_*2)   // 524416
#define SCALE 0.03125f             // D^-0.5

#define DC    32                   // d's per chunk
#define NCH   (D_/DC)              // 32 chunks
#define ROWB  136                  // bytes per token row in smem tile (128 + 8 pad)
#define TILEB (128*ROWB)           // 17408 bytes per buffer

typedef unsigned long long u64;

// ----- static scratch (no allocation) -----
__device__ __align__(16) float g_Mpart[32*8192]; // o-tile partials of M, [tile][e*1024+d]
__device__ __align__(16) float g_M[8192];        // M[e][d]  (d contiguous -> u64 d-pairs)
__device__ __align__(16) float g_c[8];
__device__ __align__(16) float g_pws[NB2*8];     // per-block softmax sums per expert
__device__ __align__(16) float g_paux[NB2];      // per-block aux partial
__device__ __align__(16) float g_m2d[64*8];      // mask2d

__device__ __forceinline__ void ffma2(u64 &d, u64 a, u64 b){
    asm("fma.rn.f32x2 %0, %1, %2, %0;" : "+l"(d) : "l"(a), "l"(b));
}
__device__ __forceinline__ float2 unpack2(u64 v){
    float2 r; asm("mov.b64 {%0,%1}, %2;" : "=f"(r.x), "=f"(r.y) : "l"(v)); return r;
}

// ================= K1: partial M[d,e] = sum_o Wq[o,d]*key[e,o] over 32-wide o-tile =========
__global__ void k1(const float* __restrict__ Wq, const float* __restrict__ key){
    __shared__ float sk[256];                  // key[e][o-tile], 8 x 32
    int tid = threadIdx.x;
    int ot = blockIdx.x & 31, dt = blockIdx.x >> 5;
    int o0 = ot << 5;
    {
        int e = tid >> 5, oo = tid & 31;
        sk[tid] = key[(e<<10) + o0 + oo];
    }
    __syncthreads();
    int d = (dt<<8) + tid;
    float acc[8] = {0.f,0.f,0.f,0.f,0.f,0.f,0.f,0.f};
    #pragma unroll 8
    for (int oo = 0; oo < 32; oo++){
        float w = Wq[(size_t)(o0+oo)*D_ + d];  // coalesced in d
        #pragma unroll
        for (int e = 0; e < 8; e++) acc[e] = fmaf(w, sk[(e<<5)+oo], acc[e]);
    }
    #pragma unroll
    for (int e = 0; e < 8; e++)
        g_Mpart[ot*8192 + (e<<10) + d] = acc[e];
}

// ================= K1b: reduce 32 partials -> g_M; compute c[e] = key[e]·bq =================
__global__ void k1b(const float* __restrict__ key, const float* __restrict__ bq){
    int i = blockIdx.x*256 + threadIdx.x;      // 0..8191  (= e*1024+d)
    float t = 0.f;
    #pragma unroll
    for (int k = 0; k < 32; k++) t += g_Mpart[k*8192 + i];
    g_M[i] = t;

    if (blockIdx.x == 0){
        int e = threadIdx.x >> 5, lane = threadIdx.x & 31;
        float c = 0.f;
        for (int o = lane; o < D_; o += 32) c = fmaf(key[(e<<10)+o], bq[o], c);
        #pragma unroll
        for (int off = 16; off > 0; off >>= 1)
            c += __shfl_xor_sync(0xffffffffu, c, off);
        if (lane == 0) g_c[e] = c;
    }
}

// ================= K2: register-tiled projection + softmax =================
// 1 warp per block; block owns 128 tokens, lane owns 4 (token = blk*128 + g*32 + lane).
// x staged gmem->smem per 32-d chunk via cp.async (8B ops, row pad 136B -> conflict-free
// LDS.64 across lanes). M read as uniform-address u64 d-pairs (__ldg broadcast): 8 loads
// per d-pair serve 128 tokens. No cross-lane score reduction; softmax fully in-lane.
__global__ void __launch_bounds__(32) k2(const float* __restrict__ x){
    __shared__ __align__(16) char tile[2*TILEB];
    int lane = threadIdx.x;
    int blk  = blockIdx.x;
    const float* xb = x + (size_t)blk*128*D_;

    // ---- prologue: issue chunk 0 ----
    {
        int r0 = lane >> 4, c8 = lane & 15;
        #pragma unroll
        for (int i = 0; i < 64; i++){
            int r = i*2 + r0;
            const float* src = xb + (size_t)r*D_ + c8*2;
            unsigned dst = (unsigned)__cvta_generic_to_shared(&tile[r*ROWB + c8*8]);
            asm volatile("cp.async.ca.shared.global [%0], [%1], 8;" :: "r"(dst), "l"(src));
        }
        asm volatile("cp.async.commit_group;");
    }

    const u64* gM64 = (const u64*)g_M;
    u64 acc[4][8];
    #pragma unroll
    for (int g = 0; g < 4; g++)
        #pragma unroll
        for (int e = 0; e < 8; e++) acc[g][e] = 0ULL;

    for (int ch = 0; ch < NCH; ch++){
        __syncwarp();   // all lanes done reading the buffer about to be overwritten
        if (ch + 1 < NCH){
            int bf = (ch + 1) & 1;
            int r0 = lane >> 4, c8 = lane & 15;
            #pragma unroll
            for (int i = 0; i < 64; i++){
                int r = i*2 + r0;
                const float* src = xb + (size_t)r*D_ + (ch+1)*DC + c8*2;
                unsigned dst = (unsigned)__cvta_generic_to_shared(&tile[bf*TILEB + r*ROWB + c8*8]);
                asm volatile("cp.async.ca.shared.global [%0], [%1], 8;" :: "r"(dst), "l"(src));
            }
            asm volatile("cp.async.commit_group;");
            asm volatile("cp.async.wait_group 1;");
        } else {
            asm volatile("cp.async.wait_group 0;");
        }
        __syncwarp();

        const char* tb = tile + (ch & 1)*TILEB;
        #pragma unroll
        for (int dp = 0; dp < DC/2; dp++){
            int gdp = (ch<<4) + dp;
            u64 mv[8];
            #pragma unroll
            for (int e = 0; e < 8; e++) mv[e] = __ldg(gM64 + (e<<9) + gdp);
            #pragma unroll
            for (int g = 0; g < 4; g++){
                u64 xv = *(const u64*)(tb + (g*32 + lane)*ROWB + dp*8);
                #pragma unroll
                for (int e = 0; e < 8; e++) ffma2(acc[g][e], xv, mv[e]);
            }
        }
    }

    // ---- per-lane epilogue: 4 complete softmaxes ----
    float creg[8];
    #pragma unroll
    for (int e = 0; e < 8; e++) creg[e] = __ldg(&g_c[e]);

    float pw[8] = {0.f,0.f,0.f,0.f,0.f,0.f,0.f,0.f};
    float pa = 0.f;
    #pragma unroll
    for (int g = 0; g < 4; g++){
        float s[8];
        #pragma unroll
        for (int e = 0; e < 8; e++){
            float2 p = unpack2(acc[g][e]);
            s[e] = (p.x + p.y + creg[e]) * SCALE;
        }
        float mx = s[0];
        #pragma unroll
        for (int e = 1; e < 8; e++) mx = fmaxf(mx, s[e]);
        float w[8], sum = 0.f;
        #pragma unroll
        for (int e = 0; e < 8; e++){ w[e] = __expf(s[e] - mx); sum += w[e]; }
        float inv = 1.0f / sum;
        #pragma unroll
        for (int e = 0; e < 8; e++){
            w[e] *= inv;
            pa += w[e] * __logf(w[e] + 1e-9f);
            pw[e] += w[e];
        }
    }

    // warp butterfly -> block partials
    #pragma unroll
    for (int off = 16; off > 0; off >>= 1){
        #pragma unroll
        for (int e = 0; e < 8; e++) pw[e] += __shfl_xor_sync(0xffffffffu, pw[e], off);
        pa += __shfl_xor_sync(0xffffffffu, pa, off);
    }
    if (lane == 0){
        #pragma unroll
        for (int e = 0; e < 8; e++) g_pws[blk*8 + e] = pw[e];
        g_paux[blk] = pa;
    }
}

// ================= K3: per-batch top-2, mask2d, indices, router loss (512 thr) =================
__global__ void __launch_bounds__(512) k3(float* __restrict__ out, int out_size){
    __shared__ float ssc[64][9];
    __shared__ float sm2[64][8];
    __shared__ float sauxw[16];
    __shared__ float scnt[8];
    int tid = threadIdx.x;
    int lane = tid & 31, warp = tid >> 5;

    // aux reduction over 512 block partials: 1 load per thread
    float a = g_paux[tid];
    #pragma unroll
    for (int off = 16; off > 0; off >>= 1)
        a += __shfl_xor_sync(0xffffffffu, a, off);
    if (lane == 0) sauxw[warp] = a;

    // per-(b,e) score: 8 independent coalesced loads
    {
        int b = tid >> 3, e = tid & 7;
        float sc = 0.f;
        #pragma unroll
        for (int j = 0; j < 8; j++) sc += g_pws[((b<<3)+j)*8 + e];
        ssc[b][e] = sc;
    }
    __syncthreads();

    if (tid < 64){
        int b = tid;
        float sc[8];
        #pragma unroll
        for (int e = 0; e < 8; e++) sc[e] = ssc[b][e];
        // top-2, ties -> lowest index (matches jax.lax.top_k)
        int i1 = 0; float v1 = sc[0];
        #pragma unroll
        for (int e = 1; e < 8; e++) if (sc[e] > v1){ v1 = sc[e]; i1 = e; }
        int i2 = -1; float v2 = -3.0e38f;
        #pragma unroll
        for (int e = 0; e < 8; e++) if (e != i1 && sc[e] > v2){ v2 = sc[e]; i2 = e; }
        #pragma unroll
        for (int e = 0; e < 8; e++){
            float mv = (e == i1 || e == i2) ? 1.f : 0.f;
            sm2[b][e] = mv;
            g_m2d[b*8 + e] = mv;
        }
        if (out_size > IDX_OFF + b*2 + 1){
            out[IDX_OFF + b*2 + 0] = (float)i1;
            out[IDX_OFF + b*2 + 1] = (float)i2;
        }
    }
    __syncthreads();

    if (tid < 8){
        float c = 0.f;
        #pragma unroll
        for (int b = 0; b < 64; b++) c += sm2[b][tid];
        scnt[tid] = c;
    }
    __syncthreads();

    if (tid == 0){
        float auxtot = 0.f;
        #pragma unroll
        for (int wp = 0; wp < 16; wp++) auxtot += sauxw[wp];
        float kl = 0.f;
        const float ip = 0.125f;
        const float lip = logf(0.125f);
        #pragma unroll
        for (int e = 0; e < 8; e++){
            float usage = scnt[e] * (1.0f/64.0f);   // mask2d.sum(0) * S/(B*S)
            kl += ip * (lip - logf(usage));
        }
        kl *= 0.125f;                               // batchmean over E
        float auxm = auxtot * (1.0f / (float)(B_*S_*E_));
        if (out_size > LOSS_OFF)
            out[LOSS_OFF] = 1e-3f*kl + 1e-3f*auxm;
    }
}

// ================= K4: broadcast mask2d -> mask[B,S,E] =================
__global__ void __launch_bounds__(256) k4(float* __restrict__ out){
    int t = blockIdx.x*256 + threadIdx.x;   // 0..65535 (b,s) pairs
    int b = t >> 10;
    const float4* m = (const float4*)g_m2d;
    float4 a0 = __ldg(&m[b*2 + 0]);
    float4 a1 = __ldg(&m[b*2 + 1]);
    float4* o = (float4*)out;
    o[t*2 + 0] = a0;
    o[t*2 + 1] = a1;
}

extern "C" void kernel_launch(void* const* d_in, const int* in_sizes, int n_in,
                              void* d_out, int out_size){
    (void)in_sizes; (void)n_in;
    const float* x   = (const float*)d_in[0];
    const float* Wq  = (const float*)d_in[1];
    const float* bq  = (const float*)d_in[2];
    const float* key = (const float*)d_in[3];
    float* out = (float*)d_out;

    k1 <<<128,  256>>>(Wq, key);
    k1b<<<32,   256>>>(key, bq);
    k2 <<<NB2,  32>>>(x);
    k3 <<<1,    512>>>(out, out_size);
    k4 <<<256,  256>>>(out);
}

// round 14
// speedup vs baseline: 1.1350x; 1.1350x over previous
#include <cuda_runtime.h>
#include <math.h>

#define D_    1024
#define E_    8
#define B_    64
#define S_    1024
#define NTOK  65536
#define NB2   512                  // K2 blocks: 128 tokens each (8 blocks/batch)
#define MASK_N   (B_*S_*E_)        // 524288
#define IDX_OFF  MASK_N
#define LOSS_OFF (MASK_N + B_*2)   // 524416
#define SCALE 0.03125f             // D^-0.5

#define DC    32                   // d's per chunk
#define NCH   (D_/DC)              // 32 chunks
#define TOKB  128                  // tokens per block
#define ROWB  144                  // bytes per token row in smem tile (128 + 16 pad, 16B-aligned)
#define TILEB (TOKB*ROWB)          // 18432 bytes per buffer

typedef unsigned long long u64;

// ----- static scratch (no allocation) -----
__device__ __align__(16) float g_Mpart[32*8192]; // o-tile partials of M, [tile][e*1024+d]
__device__ __align__(16) float g_M[8192];        // M[e][d]  (d contiguous)
__device__ __align__(16) float g_c[8];
__device__ __align__(16) float g_pws[NB2*8];     // per-block softmax sums per expert
__device__ __align__(16) float g_paux[NB2];      // per-block aux partial
__device__ __align__(16) float g_m2d[64*8];      // mask2d

__device__ __forceinline__ void ffma2(u64 &d, u64 a, u64 b){
    asm("fma.rn.f32x2 %0, %1, %2, %0;" : "+l"(d) : "l"(a), "l"(b));
}
__device__ __forceinline__ float2 unpack2(u64 v){
    float2 r; asm("mov.b64 {%0,%1}, %2;" : "=f"(r.x), "=f"(r.y) : "l"(v)); return r;
}
union U4 { uint4 v; u64 u[2]; };

// ================= K1: partial M[d,e] = sum_o Wq[o,d]*key[e,o] over 32-wide o-tile =========
__global__ void k1(const float* __restrict__ Wq, const float* __restrict__ key){
    __shared__ float sk[256];                  // key[e][o-tile], 8 x 32
    int tid = threadIdx.x;
    int ot = blockIdx.x & 31, dt = blockIdx.x >> 5;
    int o0 = ot << 5;
    {
        int e = tid >> 5, oo = tid & 31;
        sk[tid] = key[(e<<10) + o0 + oo];
    }
    __syncthreads();
    int d = (dt<<8) + tid;
    float acc[8] = {0.f,0.f,0.f,0.f,0.f,0.f,0.f,0.f};
    #pragma unroll 8
    for (int oo = 0; oo < 32; oo++){
        float w = Wq[(size_t)(o0+oo)*D_ + d];  // coalesced in d
        #pragma unroll
        for (int e = 0; e < 8; e++) acc[e] = fmaf(w, sk[(e<<5)+oo], acc[e]);
    }
    #pragma unroll
    for (int e = 0; e < 8; e++)
        g_Mpart[ot*8192 + (e<<10) + d] = acc[e];
}

// ================= K1b: reduce 32 partials -> g_M; compute c[e] = key[e]·bq =================
__global__ void k1b(const float* __restrict__ key, const float* __restrict__ bq){
    int i = blockIdx.x*256 + threadIdx.x;      // 0..8191  (= e*1024+d)
    float t = 0.f;
    #pragma unroll
    for (int k = 0; k < 32; k++) t += g_Mpart[k*8192 + i];
    g_M[i] = t;

    if (blockIdx.x == 0){
        int e = threadIdx.x >> 5, lane = threadIdx.x & 31;
        float c = 0.f;
        for (int o = lane; o < D_; o += 32) c = fmaf(key[(e<<10)+o], bq[o], c);
        #pragma unroll
        for (int off = 16; off > 0; off >>= 1)
            c += __shfl_xor_sync(0xffffffffu, c, off);
        if (lane == 0) g_c[e] = c;
    }
}

// ================= K2: token-per-lane projection + softmax =================
// 512 blocks x 64 threads (2 warps). Block owns 128 tokens; lane owns 2
// (token = blk*128 + warp*64 + g*32 + lane). x staged per 32-d chunk via 16B
// cp.async.cg (L1-bypassing, double-buffered); lane reads only its own tokens'
// x (LDS.128 at 4-phase floor). M read as uniform ulonglong2 __ldg broadcasts
// (L1-resident): one 8-load group serves 64 tokens. Softmax fully in-lane.
__global__ void __launch_bounds__(64) k2(const float* __restrict__ x){
    __shared__ __align__(16) char tile[2*TILEB];
    int tid  = threadIdx.x;
    int lane = tid & 31, warp = tid >> 5;
    int blk  = blockIdx.x;
    const float* xb = x + (size_t)blk*TOKB*D_;

    // stage chunk ch into buffer ch&1: 128 rows x 128B, 8 threads per row
    auto issue = [&](int ch){
        int bf = ch & 1;
        #pragma unroll
        for (int i = 0; i < 16; i++){
            int idx = i*64 + tid;
            int row = idx >> 3, c16 = idx & 7;
            const float* src = xb + (size_t)row*D_ + ch*DC + c16*4;
            unsigned dst = (unsigned)__cvta_generic_to_shared(
                &tile[bf*TILEB + row*ROWB + c16*16]);
            asm volatile("cp.async.cg.shared.global [%0], [%1], 16;"
                         :: "r"(dst), "l"(src));
        }
        asm volatile("cp.async.commit_group;");
    };

    issue(0);

    const ulonglong2* M16 = (const ulonglong2*)g_M;   // 256 per e-row
    u64 acc[2][8];
    #pragma unroll
    for (int g = 0; g < 2; g++)
        #pragma unroll
        for (int e = 0; e < 8; e++) acc[g][e] = 0ULL;

    int base0 = (warp*64 +  0 + lane)*ROWB;
    int base1 = (warp*64 + 32 + lane)*ROWB;

    for (int ch = 0; ch < NCH; ch++){
        if (ch + 1 < NCH){
            issue(ch + 1);
            asm volatile("cp.async.wait_group 1;");
        } else {
            asm volatile("cp.async.wait_group 0;");
        }
        __syncthreads();

        const char* tb = tile + (ch & 1)*TILEB;
        #pragma unroll
        for (int dp2 = 0; dp2 < 8; dp2++){
            ulonglong2 mv[8];
            #pragma unroll
            for (int e = 0; e < 8; e++)
                mv[e] = __ldg(M16 + (e<<8) + ch*8 + dp2);
            U4 xv0, xv1;
            xv0.v = *(const uint4*)(tb + base0 + dp2*16);
            xv1.v = *(const uint4*)(tb + base1 + dp2*16);
            #pragma unroll
            for (int e = 0; e < 8; e++){
                ffma2(acc[0][e], xv0.u[0], mv[e].x);
                ffma2(acc[0][e], xv0.u[1], mv[e].y);
                ffma2(acc[1][e], xv1.u[0], mv[e].x);
                ffma2(acc[1][e], xv1.u[1], mv[e].y);
            }
        }
        __syncthreads();   // all warps done with this buffer before it's re-issued
    }

    // ---- per-lane epilogue: 2 complete softmaxes ----
    float creg[8];
    #pragma unroll
    for (int e = 0; e < 8; e++) creg[e] = __ldg(&g_c[e]);

    float pw[8] = {0.f,0.f,0.f,0.f,0.f,0.f,0.f,0.f};
    float pa = 0.f;
    #pragma unroll
    for (int g = 0; g < 2; g++){
        float s[8];
        #pragma unroll
        for (int e = 0; e < 8; e++){
            float2 p = unpack2(acc[g][e]);
            s[e] = (p.x + p.y + creg[e]) * SCALE;
        }
        float mx = s[0];
        #pragma unroll
        for (int e = 1; e < 8; e++) mx = fmaxf(mx, s[e]);
        float w[8], sum = 0.f;
        #pragma unroll
        for (int e = 0; e < 8; e++){ w[e] = __expf(s[e] - mx); sum += w[e]; }
        float inv = 1.0f / sum;
        #pragma unroll
        for (int e = 0; e < 8; e++){
            w[e] *= inv;
            pa += w[e] * __logf(w[e] + 1e-9f);
            pw[e] += w[e];
        }
    }

    // warp butterfly, then combine the 2 warps via smem
    #pragma unroll
    for (int off = 16; off > 0; off >>= 1){
        #pragma unroll
        for (int e = 0; e < 8; e++) pw[e] += __shfl_xor_sync(0xffffffffu, pw[e], off);
        pa += __shfl_xor_sync(0xffffffffu, pa, off);
    }
    __shared__ float sRed[2][9];
    if (lane == 0){
        #pragma unroll
        for (int e = 0; e < 8; e++) sRed[warp][e] = pw[e];
        sRed[warp][8] = pa;
    }
    __syncthreads();
    if (tid < 9){
        float t = sRed[0][tid] + sRed[1][tid];
        if (tid < 8) g_pws[blk*8 + tid] = t;
        else         g_paux[blk]        = t;
    }
}

// ================= K3: per-batch top-2, mask2d, indices, router loss (512 thr) =================
__global__ void __launch_bounds__(512) k3(float* __restrict__ out, int out_size){
    __shared__ float ssc[64][9];
    __shared__ float sm2[64][8];
    __shared__ float sauxw[16];
    __shared__ float scnt[8];
    int tid = threadIdx.x;
    int lane = tid & 31, warp = tid >> 5;

    // aux reduction over 512 block partials: 1 load per thread
    float a = g_paux[tid];
    #pragma unroll
    for (int off = 16; off > 0; off >>= 1)
        a += __shfl_xor_sync(0xffffffffu, a, off);
    if (lane == 0) sauxw[warp] = a;

    // per-(b,e) score: 8 independent coalesced loads
    {
        int b = tid >> 3, e = tid & 7;
        float sc = 0.f;
        #pragma unroll
        for (int j = 0; j < 8; j++) sc += g_pws[((b<<3)+j)*8 + e];
        ssc[b][e] = sc;
    }
    __syncthreads();

    if (tid < 64){
        int b = tid;
        float sc[8];
        #pragma unroll
        for (int e = 0; e < 8; e++) sc[e] = ssc[b][e];
        // top-2, ties -> lowest index (matches jax.lax.top_k)
        int i1 = 0; float v1 = sc[0];
        #pragma unroll
        for (int e = 1; e < 8; e++) if (sc[e] > v1){ v1 = sc[e]; i1 = e; }
        int i2 = -1; float v2 = -3.0e38f;
        #pragma unroll
        for (int e = 0; e < 8; e++) if (e != i1 && sc[e] > v2){ v2 = sc[e]; i2 = e; }
        #pragma unroll
        for (int e = 0; e < 8; e++){
            float mv = (e == i1 || e == i2) ? 1.f : 0.f;
            sm2[b][e] = mv;
            g_m2d[b*8 + e] = mv;
        }
        if (out_size > IDX_OFF + b*2 + 1){
            out[IDX_OFF + b*2 + 0] = (float)i1;
            out[IDX_OFF + b*2 + 1] = (float)i2;
        }
    }
    __syncthreads();

    if (tid < 8){
        float c = 0.f;
        #pragma unroll
        for (int b = 0; b < 64; b++) c += sm2[b][tid];
        scnt[tid] = c;
    }
    __syncthreads();

    if (tid == 0){
        float auxtot = 0.f;
        #pragma unroll
        for (int wp = 0; wp < 16; wp++) auxtot += sauxw[wp];
        float kl = 0.f;
        const float ip = 0.125f;
        const float lip = logf(0.125f);
        #pragma unroll
        for (int e = 0; e < 8; e++){
            float usage = scnt[e] * (1.0f/64.0f);   // mask2d.sum(0) * S/(B*S)
            kl += ip * (lip - logf(usage));
        }
        kl *= 0.125f;                               // batchmean over E
        float auxm = auxtot * (1.0f / (float)(B_*S_*E_));
        if (out_size > LOSS_OFF)
            out[LOSS_OFF] = 1e-3f*kl + 1e-3f*auxm;
    }
}

// ================= K4: broadcast mask2d -> mask[B,S,E] =================
__global__ void __launch_bounds__(256) k4(float* __restrict__ out){
    int t = blockIdx.x*256 + threadIdx.x;   // 0..65535 (b,s) pairs
    int b = t >> 10;
    const float4* m = (const float4*)g_m2d;
    float4 a0 = __ldg(&m[b*2 + 0]);
    float4 a1 = __ldg(&m[b*2 + 1]);
    float4* o = (float4*)out;
    o[t*2 + 0] = a0;
    o[t*2 + 1] = a1;
}

extern "C" void kernel_launch(void* const* d_in, const int* in_sizes, int n_in,
                              void* d_out, int out_size){
    (void)in_sizes; (void)n_in;
    const float* x   = (const float*)d_in[0];
    const float* Wq  = (const float*)d_in[1];
    const float* bq  = (const float*)d_in[2];
    const float* key = (const float*)d_in[3];
    float* out = (float*)d_out;

    k1 <<<128,  256>>>(Wq, key);
    k1b<<<32,   256>>>(key, bq);
    k2 <<<NB2,  64>>>(x);
    k3 <<<1,    512>>>(out, out_size);
    k4 <<<256,  256>>>(out);
}

// round 15
// speedup vs baseline: 1.4308x; 1.2606x over previous
#include <cuda_runtime.h>
#include <math.h>

#define D_    1024
#define E_    8
#define B_    64
#define S_    1024
#define NB2   512                  // K2 blocks: 128 tokens each (8 blocks/batch)
#define MASK_N   (B_*S_*E_)        // 524288
#define IDX_OFF  MASK_N
#define LOSS_OFF (MASK_N + B_*2)   // 524416
#define SCALE 0.03125f             // D^-0.5

#define DC     32                  // d's per chunk
#define NCH    (D_/DC)             // 32 chunks
#define ROWB   144                 // bytes per token row in a stage (128 + 16 pad)
#define STAGEB (32*ROWB)           // 4608 B: one warp-stage (32 rows)
#define WTILEB (4*STAGEB)          // 18432 B: 4 stages per warp
#define MSMEM  32768               // M copy in smem
#define SMEMSZ (MSMEM + 4*WTILEB)  // 106496 B dynamic smem

typedef unsigned long long u64;

// ----- static scratch (no allocation) -----
__device__ __align__(16) float g_Mpart[32*8192]; // o-tile partials of M
__device__ __align__(16) float g_M[8192];        // M[e][d] (d contiguous)
__device__ __align__(16) float g_c[8];
__device__ __align__(16) float g_pws[NB2*8];     // per-block softmax sums per expert
__device__ __align__(16) float g_paux[NB2];      // per-block aux partial
__device__ __align__(16) float g_m2d[64*8];      // mask2d

__device__ __forceinline__ void ffma2(u64 &d, u64 a, u64 b){
    asm("fma.rn.f32x2 %0, %1, %2, %0;" : "+l"(d) : "l"(a), "l"(b));
}
__device__ __forceinline__ float2 unpack2(u64 v){
    float2 r; asm("mov.b64 {%0,%1}, %2;" : "=f"(r.x), "=f"(r.y) : "l"(v)); return r;
}
union U4 { uint4 v; u64 u[2]; };

// ================= K1: partial M[d,e] = sum_o Wq[o,d]*key[e,o] over 32-wide o-tile =========
__global__ void k1(const float* __restrict__ Wq, const float* __restrict__ key){
    __shared__ float sk[256];                  // key[e][o-tile], 8 x 32
    int tid = threadIdx.x;
    int ot = blockIdx.x & 31, dt = blockIdx.x >> 5;
    int o0 = ot << 5;
    {
        int e = tid >> 5, oo = tid & 31;
        sk[tid] = key[(e<<10) + o0 + oo];
    }
    __syncthreads();
    int d = (dt<<8) + tid;
    float acc[8] = {0.f,0.f,0.f,0.f,0.f,0.f,0.f,0.f};
    #pragma unroll 8
    for (int oo = 0; oo < 32; oo++){
        float w = Wq[(size_t)(o0+oo)*D_ + d];  // coalesced in d
        #pragma unroll
        for (int e = 0; e < 8; e++) acc[e] = fmaf(w, sk[(e<<5)+oo], acc[e]);
    }
    #pragma unroll
    for (int e = 0; e < 8; e++)
        g_Mpart[ot*8192 + (e<<10) + d] = acc[e];
}

// ================= K1b: reduce 32 partials -> g_M; compute c[e] = key[e]·bq =================
__global__ void k1b(const float* __restrict__ key, const float* __restrict__ bq){
    int i = blockIdx.x*256 + threadIdx.x;      // 0..8191  (= e*1024+d)
    float t = 0.f;
    #pragma unroll
    for (int k = 0; k < 32; k++) t += g_Mpart[k*8192 + i];
    g_M[i] = t;

    if (blockIdx.x == 0){
        int e = threadIdx.x >> 5, lane = threadIdx.x & 31;
        float c = 0.f;
        for (int o = lane; o < D_; o += 32) c = fmaf(key[(e<<10)+o], bq[o], c);
        #pragma unroll
        for (int off = 16; off > 0; off >>= 1)
            c += __shfl_xor_sync(0xffffffffu, c, off);
        if (lane == 0) g_c[e] = c;
    }
}

// ================= K2: warp-private pipelined projection + softmax =================
// 512 blocks x 128 threads (4 warps). Warp owns 32 tokens (lane owns 1:
// token = blk*128 + warp*32 + lane). Each warp stages ITS OWN rows per 32-d
// chunk via 16B cp.async.cg into a private 4-stage ring -> no __syncthreads in
// the mainloop; each warp free-runs depth-3 prefetch. M (32KB) copied once to
// smem; read as uniform LDS.128 broadcasts (1 phase, off the LSU queue).
__global__ void __launch_bounds__(128) k2(const float* __restrict__ x){
    extern __shared__ __align__(16) char smem[];
    int tid  = threadIdx.x;
    int lane = tid & 31, w = tid >> 5;
    int blk  = blockIdx.x;
    const float* xb = x + (size_t)(blk*128 + w*32)*D_;   // this warp's 32 rows
    char* wtile = smem + MSMEM + w*WTILEB;

    // ---- stage M into smem (all 128 threads, one group) ----
    #pragma unroll
    for (int i = 0; i < 16; i++){
        int idx = i*128 + tid;                 // 2048 x 16B = 32KB
        const float* src = g_M + idx*4;
        unsigned dst = (unsigned)__cvta_generic_to_shared(smem + idx*16);
        asm volatile("cp.async.ca.shared.global [%0], [%1], 16;" :: "r"(dst), "l"(src));
    }
    asm volatile("cp.async.commit_group;");

    // stage chunk ch into ring slot ch&3 (warp-private; 8 lanes per row)
    auto issue = [&](int ch){
        char* tb = wtile + (ch & 3)*STAGEB;
        #pragma unroll
        for (int i = 0; i < 8; i++){
            int idx = i*32 + lane;
            int r = idx >> 3, c = idx & 7;
            const float* src = xb + (size_t)r*D_ + ch*DC + c*4;
            unsigned dst = (unsigned)__cvta_generic_to_shared(tb + r*ROWB + c*16);
            asm volatile("cp.async.cg.shared.global [%0], [%1], 16;" :: "r"(dst), "l"(src));
        }
        asm volatile("cp.async.commit_group;");
    };

    issue(0); issue(1); issue(2);
    asm volatile("cp.async.wait_group 3;");    // M group complete
    __syncthreads();                           // M visible to all warps

    u64 acc[8];
    #pragma unroll
    for (int e = 0; e < 8; e++) acc[e] = 0ULL;

    for (int ch = 0; ch < NCH; ch++){
        __syncwarp();
        if (ch + 3 < NCH){
            issue(ch + 3);
            asm volatile("cp.async.wait_group 3;");   // chunk ch ready
        } else {
            asm volatile("cp.async.wait_group 0;");
        }
        __syncwarp();

        const char* tb = wtile + (ch & 3)*STAGEB;
        const char* mrow = smem + ch*128;      // + e*4096 + dp2*16
        #pragma unroll
        for (int dp2 = 0; dp2 < 8; dp2++){
            U4 xv; xv.v = *(const uint4*)(tb + lane*ROWB + dp2*16);
            #pragma unroll
            for (int e = 0; e < 8; e++){
                U4 mv; mv.v = *(const uint4*)(mrow + e*4096 + dp2*16);  // broadcast
                ffma2(acc[e], xv.u[0], mv.u[0]);
                ffma2(acc[e], xv.u[1], mv.u[1]);
            }
        }
    }

    // ---- per-lane epilogue: 1 complete softmax ----
    float pw[8], pa = 0.f;
    {
        float s[8];
        #pragma unroll
        for (int e = 0; e < 8; e++){
            float2 p = unpack2(acc[e]);
            s[e] = (p.x + p.y + __ldg(&g_c[e])) * SCALE;
        }
        float mx = s[0];
        #pragma unroll
        for (int e = 1; e < 8; e++) mx = fmaxf(mx, s[e]);
        float sum = 0.f;
        #pragma unroll
        for (int e = 0; e < 8; e++){ pw[e] = __expf(s[e] - mx); sum += pw[e]; }
        float inv = 1.0f / sum;
        #pragma unroll
        for (int e = 0; e < 8; e++){
            pw[e] *= inv;
            pa += pw[e] * __logf(pw[e] + 1e-9f);
        }
    }

    // warp butterfly, then combine 4 warps via smem
    #pragma unroll
    for (int off = 16; off > 0; off >>= 1){
        #pragma unroll
        for (int e = 0; e < 8; e++) pw[e] += __shfl_xor_sync(0xffffffffu, pw[e], off);
        pa += __shfl_xor_sync(0xffffffffu, pa, off);
    }
    __shared__ float sRed[4][9];
    if (lane == 0){
        #pragma unroll
        for (int e = 0; e < 8; e++) sRed[w][e] = pw[e];
        sRed[w][8] = pa;
    }
    __syncthreads();
    if (tid < 9){
        float t = sRed[0][tid] + sRed[1][tid] + sRed[2][tid] + sRed[3][tid];
        if (tid < 8) g_pws[blk*8 + tid] = t;
        else         g_paux[blk]        = t;
    }
}

// ================= K3: per-batch top-2, mask2d, indices, router loss (512 thr) =================
__global__ void __launch_bounds__(512) k3(float* __restrict__ out, int out_size){
    __shared__ float ssc[64][9];
    __shared__ float sm2[64][8];
    __shared__ float sauxw[16];
    __shared__ float scnt[8];
    int tid = threadIdx.x;
    int lane = tid & 31, warp = tid >> 5;

    // aux reduction over 512 block partials: 1 load per thread
    float a = g_paux[tid];
    #pragma unroll
    for (int off = 16; off > 0; off >>= 1)
        a += __shfl_xor_sync(0xffffffffu, a, off);
    if (lane == 0) sauxw[warp] = a;

    // per-(b,e) score: 8 independent coalesced loads
    {
        int b = tid >> 3, e = tid & 7;
        float sc = 0.f;
        #pragma unroll
        for (int j = 0; j < 8; j++) sc += g_pws[((b<<3)+j)*8 + e];
        ssc[b][e] = sc;
    }
    __syncthreads();

    if (tid < 64){
        int b = tid;
        float sc[8];
        #pragma unroll
        for (int e = 0; e < 8; e++) sc[e] = ssc[b][e];
        // top-2, ties -> lowest index (matches jax.lax.top_k)
        int i1 = 0; float v1 = sc[0];
        #pragma unroll
        for (int e = 1; e < 8; e++) if (sc[e] > v1){ v1 = sc[e]; i1 = e; }
        int i2 = -1; float v2 = -3.0e38f;
        #pragma unroll
        for (int e = 0; e < 8; e++) if (e != i1 && sc[e] > v2){ v2 = sc[e]; i2 = e; }
        #pragma unroll
        for (int e = 0; e < 8; e++){
            float mv = (e == i1 || e == i2) ? 1.f : 0.f;
            sm2[b][e] = mv;
            g_m2d[b*8 + e] = mv;
        }
        if (out_size > IDX_OFF + b*2 + 1){
            out[IDX_OFF + b*2 + 0] = (float)i1;
            out[IDX_OFF + b*2 + 1] = (float)i2;
        }
    }
    __syncthreads();

    if (tid < 8){
        float c = 0.f;
        #pragma unroll
        for (int b = 0; b < 64; b++) c += sm2[b][tid];
        scnt[tid] = c;
    }
    __syncthreads();

    if (tid == 0){
        float auxtot = 0.f;
        #pragma unroll
        for (int wp = 0; wp < 16; wp++) auxtot += sauxw[wp];
        float kl = 0.f;
        const float ip = 0.125f;
        const float lip = logf(0.125f);
        #pragma unroll
        for (int e = 0; e < 8; e++){
            float usage = scnt[e] * (1.0f/64.0f);   // mask2d.sum(0) * S/(B*S)
            kl += ip * (lip - logf(usage));
        }
        kl *= 0.125f;                               // batchmean over E
        float auxm = auxtot * (1.0f / (float)(B_*S_*E_));
        if (out_size > LOSS_OFF)
            out[LOSS_OFF] = 1e-3f*kl + 1e-3f*auxm;
    }
}

// ================= K4: broadcast mask2d -> mask[B,S,E] =================
__global__ void __launch_bounds__(256) k4(float* __restrict__ out){
    int t = blockIdx.x*256 + threadIdx.x;   // 0..65535 (b,s) pairs
    int b = t >> 10;
    const float4* m = (const float4*)g_m2d;
    float4 a0 = __ldg(&m[b*2 + 0]);
    float4 a1 = __ldg(&m[b*2 + 1]);
    float4* o = (float4*)out;
    o[t*2 + 0] = a0;
    o[t*2 + 1] = a1;
}

extern "C" void kernel_launch(void* const* d_in, const int* in_sizes, int n_in,
                              void* d_out, int out_size){
    (void)in_sizes; (void)n_in;
    const float* x   = (const float*)d_in[0];
    const float* Wq  = (const float*)d_in[1];
    const float* bq  = (const float*)d_in[2];
    const float* key = (const float*)d_in[3];
    float* out = (float*)d_out;

    cudaFuncSetAttribute(k2, cudaFuncAttributeMaxDynamicSharedMemorySize, SMEMSZ);

    k1 <<<128,  256>>>(Wq, key);
    k1b<<<32,   256>>>(key, bq);
    k2 <<<NB2,  128, SMEMSZ>>>(x);
    k3 <<<1,    512>>>(out, out_size);
    k4 <<<256,  256>>>(out);
}

// round 16
// speedup vs baseline: 1.5101x; 1.0554x over previous
#include <cuda_runtime.h>
#include <math.h>

#define D_    1024
#define E_    8
#define B_    64
#define S_    1024
#define NB2   256                  // K2 blocks: 256 tokens each (4 blocks/batch)
#define MASK_N   (B_*S_*E_)        // 524288
#define IDX_OFF  MASK_N
#define LOSS_OFF (MASK_N + B_*2)   // 524416
#define SCALE 0.03125f             // D^-0.5

#define DC     32                  // d's per chunk
#define NCH    (D_/DC)             // 32 chunks
#define TOKW   128                 // tokens per warp (lane owns 4)
#define ROWB   144                 // bytes per token row in a stage (128 + 16 pad)
#define STAGEB (TOKW*ROWB)         // 18432 B: one warp-stage (128 rows)
#define WTILEB (2*STAGEB)          // 36864 B: ping-pong ring per warp
#define MSMEM  32768               // M copy in smem
#define SMEMSZ (MSMEM + 2*WTILEB)  // 106496 B dynamic smem

typedef unsigned long long u64;

// ----- static scratch (no allocation) -----
__device__ __align__(16) float g_Mpart[32*8192]; // o-tile partials of M
__device__ __align__(16) float g_M[8192];        // M[e][d] (d contiguous)
__device__ __align__(16) float g_c[8];
__device__ __align__(16) float g_pws[NB2*8];     // per-block softmax sums per expert
__device__ __align__(16) float g_paux[NB2];      // per-block aux partial
__device__ __align__(16) float g_m2d[64*8];      // mask2d

__device__ __forceinline__ void ffma2(u64 &d, u64 a, u64 b){
    asm("fma.rn.f32x2 %0, %1, %2, %0;" : "+l"(d) : "l"(a), "l"(b));
}
__device__ __forceinline__ float2 unpack2(u64 v){
    float2 r; asm("mov.b64 {%0,%1}, %2;" : "=f"(r.x), "=f"(r.y) : "l"(v)); return r;
}
union U4 { uint4 v; u64 u[2]; };

// ================= K1: partial M[d,e] = sum_o Wq[o,d]*key[e,o] over 32-wide o-tile =========
__global__ void k1(const float* __restrict__ Wq, const float* __restrict__ key){
    __shared__ float sk[256];                  // key[e][o-tile], 8 x 32
    int tid = threadIdx.x;
    int ot = blockIdx.x & 31, dt = blockIdx.x >> 5;
    int o0 = ot << 5;
    {
        int e = tid >> 5, oo = tid & 31;
        sk[tid] = key[(e<<10) + o0 + oo];
    }
    __syncthreads();
    int d = (dt<<8) + tid;
    float acc[8] = {0.f,0.f,0.f,0.f,0.f,0.f,0.f,0.f};
    #pragma unroll 8
    for (int oo = 0; oo < 32; oo++){
        float w = Wq[(size_t)(o0+oo)*D_ + d];  // coalesced in d
        #pragma unroll
        for (int e = 0; e < 8; e++) acc[e] = fmaf(w, sk[(e<<5)+oo], acc[e]);
    }
    #pragma unroll
    for (int e = 0; e < 8; e++)
        g_Mpart[ot*8192 + (e<<10) + d] = acc[e];
}

// ================= K1b: reduce 32 partials -> g_M; compute c[e] = key[e]·bq =================
__global__ void k1b(const float* __restrict__ key, const float* __restrict__ bq){
    int i = blockIdx.x*256 + threadIdx.x;      // 0..8191  (= e*1024+d)
    float t = 0.f;
    #pragma unroll
    for (int k = 0; k < 32; k++) t += g_Mpart[k*8192 + i];
    g_M[i] = t;

    if (blockIdx.x == 0){
        int e = threadIdx.x >> 5, lane = threadIdx.x & 31;
        float c = 0.f;
        for (int o = lane; o < D_; o += 32) c = fmaf(key[(e<<10)+o], bq[o], c);
        #pragma unroll
        for (int off = 16; off > 0; off >>= 1)
            c += __shfl_xor_sync(0xffffffffu, c, off);
        if (lane == 0) g_c[e] = c;
    }
}

// ================= K2: G=4 warp-private pipelined projection + softmax =================
// 256 blocks x 64 threads (2 warps). Warp owns 128 tokens, lane owns 4
// (token = blk*256 + w*128 + g*32 + lane). Warp stages its own rows per 32-d
// chunk via 16B cp.async.cg into a private ping-pong ring -> no block barriers
// in the mainloop. M (32KB) in smem, uniform LDS.128 broadcasts amortized over
// 4 tokens/lane: 3 smem phases per token-chunk (vs 9 at G=1).
__global__ void __launch_bounds__(64) k2(const float* __restrict__ x){
    extern __shared__ __align__(16) char smem[];
    int tid  = threadIdx.x;
    int lane = tid & 31, w = tid >> 5;
    int blk  = blockIdx.x;
    const float* xb = x + (size_t)(blk*256 + w*TOKW)*D_;  // this warp's 128 rows
    char* wtile = smem + MSMEM + w*WTILEB;

    // ---- stage M into smem (both warps, one group) ----
    #pragma unroll
    for (int i = 0; i < 32; i++){
        int idx = i*64 + tid;                  // 2048 x 16B = 32KB
        const float* src = g_M + idx*4;
        unsigned dst = (unsigned)__cvta_generic_to_shared(smem + idx*16);
        asm volatile("cp.async.ca.shared.global [%0], [%1], 16;" :: "r"(dst), "l"(src));
    }
    asm volatile("cp.async.commit_group;");

    // stage chunk ch into ring slot ch&1 (warp-private; 8 lanes per row)
    auto issue = [&](int ch){
        char* tb = wtile + (ch & 1)*STAGEB;
        #pragma unroll
        for (int i = 0; i < 32; i++){
            int idx = i*32 + lane;
            int r = idx >> 3, c = idx & 7;
            const float* src = xb + (size_t)r*D_ + ch*DC + c*4;
            unsigned dst = (unsigned)__cvta_generic_to_shared(tb + r*ROWB + c*16);
            asm volatile("cp.async.cg.shared.global [%0], [%1], 16;" :: "r"(dst), "l"(src));
        }
        asm volatile("cp.async.commit_group;");
    };

    issue(0); issue(1);
    asm volatile("cp.async.wait_group 2;");    // M group complete
    __syncthreads();                           // M visible to both warps

    u64 acc[4][8];
    #pragma unroll
    for (int g = 0; g < 4; g++)
        #pragma unroll
        for (int e = 0; e < 8; e++) acc[g][e] = 0ULL;

    for (int ch = 0; ch < NCH; ch++){
        // chunk ch ready? pending = {ch, ch+1} -> wait 1; last iter wait 0
        if (ch + 1 < NCH) asm volatile("cp.async.wait_group 1;");
        else              asm volatile("cp.async.wait_group 0;");
        __syncwarp();

        const char* tb = wtile + (ch & 1)*STAGEB;
        const char* mrow = smem + ch*128;      // + e*4096 + dp2*16
        #pragma unroll
        for (int dp2 = 0; dp2 < 8; dp2++){
            U4 xv[4];
            #pragma unroll
            for (int g = 0; g < 4; g++)
                xv[g].v = *(const uint4*)(tb + (g*32 + lane)*ROWB + dp2*16);
            #pragma unroll
            for (int e = 0; e < 8; e++){
                U4 mv; mv.v = *(const uint4*)(mrow + e*4096 + dp2*16);  // broadcast
                #pragma unroll
                for (int g = 0; g < 4; g++){
                    ffma2(acc[g][e], xv[g].u[0], mv.u[0]);
                    ffma2(acc[g][e], xv[g].u[1], mv.u[1]);
                }
            }
        }

        __syncwarp();      // all lanes done reading slot ch&1 before re-staging it
        if (ch + 2 < NCH) issue(ch + 2);
    }

    // ---- per-lane epilogue: 4 complete softmaxes ----
    float creg[8];
    #pragma unroll
    for (int e = 0; e < 8; e++) creg[e] = __ldg(&g_c[e]);

    float pw[8] = {0.f,0.f,0.f,0.f,0.f,0.f,0.f,0.f};
    float pa = 0.f;
    #pragma unroll
    for (int g = 0; g < 4; g++){
        float s[8];
        #pragma unroll
        for (int e = 0; e < 8; e++){
            float2 p = unpack2(acc[g][e]);
            s[e] = (p.x + p.y + creg[e]) * SCALE;
        }
        float mx = s[0];
        #pragma unroll
        for (int e = 1; e < 8; e++) mx = fmaxf(mx, s[e]);
        float wv[8], sum = 0.f;
        #pragma unroll
        for (int e = 0; e < 8; e++){ wv[e] = __expf(s[e] - mx); sum += wv[e]; }
        float inv = 1.0f / sum;
        #pragma unroll
        for (int e = 0; e < 8; e++){
            wv[e] *= inv;
            pa += wv[e] * __logf(wv[e] + 1e-9f);
            pw[e] += wv[e];
        }
    }

    // warp butterfly, then combine 2 warps via smem
    #pragma unroll
    for (int off = 16; off > 0; off >>= 1){
        #pragma unroll
        for (int e = 0; e < 8; e++) pw[e] += __shfl_xor_sync(0xffffffffu, pw[e], off);
        pa += __shfl_xor_sync(0xffffffffu, pa, off);
    }
    __shared__ float sRed[2][9];
    if (lane == 0){
        #pragma unroll
        for (int e = 0; e < 8; e++) sRed[w][e] = pw[e];
        sRed[w][8] = pa;
    }
    __syncthreads();
    if (tid < 9){
        float t = sRed[0][tid] + sRed[1][tid];
        if (tid < 8) g_pws[blk*8 + tid] = t;
        else         g_paux[blk]        = t;
    }
}

// ================= K3: per-batch top-2, mask2d, indices, router loss (512 thr) =================
__global__ void __launch_bounds__(512) k3(float* __restrict__ out, int out_size){
    __shared__ float ssc[64][9];
    __shared__ float sm2[64][8];
    __shared__ float sauxw[16];
    __shared__ float scnt[8];
    int tid = threadIdx.x;
    int lane = tid & 31, warp = tid >> 5;

    // aux reduction over 256 block partials
    float a = (tid < NB2) ? g_paux[tid] : 0.f;
    #pragma unroll
    for (int off = 16; off > 0; off >>= 1)
        a += __shfl_xor_sync(0xffffffffu, a, off);
    if (lane == 0) sauxw[warp] = a;

    // per-(b,e) score: 4 independent coalesced loads
    {
        int b = tid >> 3, e = tid & 7;
        float sc = 0.f;
        #pragma unroll
        for (int j = 0; j < 4; j++) sc += g_pws[((b<<2)+j)*8 + e];
        ssc[b][e] = sc;
    }
    __syncthreads();

    if (tid < 64){
        int b = tid;
        float sc[8];
        #pragma unroll
        for (int e = 0; e < 8; e++) sc[e] = ssc[b][e];
        // top-2, ties -> lowest index (matches jax.lax.top_k)
        int i1 = 0; float v1 = sc[0];
        #pragma unroll
        for (int e = 1; e < 8; e++) if (sc[e] > v1){ v1 = sc[e]; i1 = e; }
        int i2 = -1; float v2 = -3.0e38f;
        #pragma unroll
        for (int e = 0; e < 8; e++) if (e != i1 && sc[e] > v2){ v2 = sc[e]; i2 = e; }
        #pragma unroll
        for (int e = 0; e < 8; e++){
            float mv = (e == i1 || e == i2) ? 1.f : 0.f;
            sm2[b][e] = mv;
            g_m2d[b*8 + e] = mv;
        }
        if (out_size > IDX_OFF + b*2 + 1){
            out[IDX_OFF + b*2 + 0] = (float)i1;
            out[IDX_OFF + b*2 + 1] = (float)i2;
        }
    }
    __syncthreads();

    if (tid < 8){
        float c = 0.f;
        #pragma unroll
        for (int b = 0; b < 64; b++) c += sm2[b][tid];
        scnt[tid] = c;
    }
    __syncthreads();

    if (tid == 0){
        float auxtot = 0.f;
        #pragma unroll
        for (int wp = 0; wp < 16; wp++) auxtot += sauxw[wp];
        float kl = 0.f;
        const float ip = 0.125f;
        const float lip = logf(0.125f);
        #pragma unroll
        for (int e = 0; e < 8; e++){
            float usage = scnt[e] * (1.0f/64.0f);   // mask2d.sum(0) * S/(B*S)
            kl += ip * (lip - logf(usage));
        }
        kl *= 0.125f;                               // batchmean over E
        float auxm = auxtot * (1.0f / (float)(B_*S_*E_));
        if (out_size > LOSS_OFF)
            out[LOSS_OFF] = 1e-3f*kl + 1e-3f*auxm;
    }
}

// ================= K4: broadcast mask2d -> mask[B,S,E] =================
__global__ void __launch_bounds__(256) k4(float* __restrict__ out){
    int t = blockIdx.x*256 + threadIdx.x;   // 0..65535 (b,s) pairs
    int b = t >> 10;
    const float4* m = (const float4*)g_m2d;
    float4 a0 = __ldg(&m[b*2 + 0]);
    float4 a1 = __ldg(&m[b*2 + 1]);
    float4* o = (float4*)out;
    o[t*2 + 0] = a0;
    o[t*2 + 1] = a1;
}

extern "C" void kernel_launch(void* const* d_in, const int* in_sizes, int n_in,
                              void* d_out, int out_size){
    (void)in_sizes; (void)n_in;
    const float* x   = (const float*)d_in[0];
    const float* Wq  = (const float*)d_in[1];
    const float* bq  = (const float*)d_in[2];
    const float* key = (const float*)d_in[3];
    float* out = (float*)d_out;

    cudaFuncSetAttribute(k2, cudaFuncAttributeMaxDynamicSharedMemorySize, SMEMSZ);

    k1 <<<128,  256>>>(Wq, key);
    k1b<<<32,   256>>>(key, bq);
    k2 <<<NB2,  64, SMEMSZ>>>(x);
    k3 <<<1,    512>>>(out, out_size);
    k4 <<<256,  256>>>(out);
}

// round 17
// speedup vs baseline: 1.5583x; 1.0319x over previous
#include <cuda_runtime.h>
#include <math.h>

#define D_    1024
#define E_    8
#define B_    64
#define S_    1024
#define NB2   128                  // K2 blocks: 512 tokens each (2 blocks/batch), single wave
#define MASK_N   (B_*S_*E_)        // 524288
#define IDX_OFF  MASK_N
#define LOSS_OFF (MASK_N + B_*2)   // 524416
#define SCALE 0.03125f             // D^-0.5

#define DC     32                  // d's per chunk
#define NCH    (D_/DC)             // 32 chunks
#define TOKW   128                 // tokens per warp (lane owns 4)
#define ROWB   144                 // bytes per token row in a stage (128 + 16 pad)
#define STAGEB (TOKW*ROWB)         // 18432 B: one warp-stage (128 rows)
#define WTILEB (2*STAGEB)          // 36864 B: ping-pong ring per warp
#define MSMEM  32768               // M copy in smem
#define SMEMSZ (MSMEM + 4*WTILEB)  // 180224 B dynamic smem (1 block/SM, 4 warps -> 4 SMSPs)

typedef unsigned long long u64;

// ----- static scratch (no allocation) -----
__device__ __align__(16) float g_Mpart[32*8192]; // o-tile partials of M
__device__ __align__(16) float g_M[8192];        // M[e][d] (d contiguous)
__device__ __align__(16) float g_c[8];
__device__ __align__(16) float g_pws[NB2*8];     // per-block softmax sums per expert
__device__ __align__(16) float g_paux[NB2];      // per-block aux partial
__device__ __align__(16) float g_m2d[64*8];      // mask2d

__device__ __forceinline__ void ffma2(u64 &d, u64 a, u64 b){
    asm("fma.rn.f32x2 %0, %1, %2, %0;" : "+l"(d) : "l"(a), "l"(b));
}
__device__ __forceinline__ float2 unpack2(u64 v){
    float2 r; asm("mov.b64 {%0,%1}, %2;" : "=f"(r.x), "=f"(r.y) : "l"(v)); return r;
}
union U4 { uint4 v; u64 u[2]; };

// ================= K1: partial M[d,e] = sum_o Wq[o,d]*key[e,o] over 32-wide o-tile =========
__global__ void k1(const float* __restrict__ Wq, const float* __restrict__ key){
    __shared__ float sk[256];                  // key[e][o-tile], 8 x 32
    int tid = threadIdx.x;
    int ot = blockIdx.x & 31, dt = blockIdx.x >> 5;
    int o0 = ot << 5;
    {
        int e = tid >> 5, oo = tid & 31;
        sk[tid] = key[(e<<10) + o0 + oo];
    }
    __syncthreads();
    int d = (dt<<8) + tid;
    float acc[8] = {0.f,0.f,0.f,0.f,0.f,0.f,0.f,0.f};
    #pragma unroll 8
    for (int oo = 0; oo < 32; oo++){
        float w = Wq[(size_t)(o0+oo)*D_ + d];  // coalesced in d
        #pragma unroll
        for (int e = 0; e < 8; e++) acc[e] = fmaf(w, sk[(e<<5)+oo], acc[e]);
    }
    #pragma unroll
    for (int e = 0; e < 8; e++)
        g_Mpart[ot*8192 + (e<<10) + d] = acc[e];
}

// ================= K1b: reduce 32 partials -> g_M; compute c[e] = key[e]·bq =================
__global__ void k1b(const float* __restrict__ key, const float* __restrict__ bq){
    int i = blockIdx.x*256 + threadIdx.x;      // 0..8191  (= e*1024+d)
    float t = 0.f;
    #pragma unroll
    for (int k = 0; k < 32; k++) t += g_Mpart[k*8192 + i];
    g_M[i] = t;

    if (blockIdx.x == 0){
        int e = threadIdx.x >> 5, lane = threadIdx.x & 31;
        float c = 0.f;
        for (int o = lane; o < D_; o += 32) c = fmaf(key[(e<<10)+o], bq[o], c);
        #pragma unroll
        for (int off = 16; off > 0; off >>= 1)
            c += __shfl_xor_sync(0xffffffffu, c, off);
        if (lane == 0) g_c[e] = c;
    }
}

// ================= K2: G=4 warp-private pipelined projection + softmax =================
// 128 blocks x 128 threads (4 warps, one per SMSP). Warp owns 128 tokens, lane
// owns 4 (token = blk*512 + w*128 + g*32 + lane). Warp stages its own rows per
// 32-d chunk via 16B cp.async.cg into a private ping-pong ring -> no block
// barriers in the mainloop. M (32KB) in smem, uniform LDS.128 broadcasts
// amortized over 4 tokens/lane. Single wave: 128 blocks on 148 SMs.
__global__ void __launch_bounds__(128) k2(const float* __restrict__ x){
    extern __shared__ __align__(16) char smem[];
    int tid  = threadIdx.x;
    int lane = tid & 31, w = tid >> 5;
    int blk  = blockIdx.x;
    const float* xb = x + (size_t)(blk*512 + w*TOKW)*D_;  // this warp's 128 rows
    char* wtile = smem + MSMEM + w*WTILEB;

    // ---- stage M into smem (all 4 warps, one group) ----
    #pragma unroll
    for (int i = 0; i < 16; i++){
        int idx = i*128 + tid;                 // 2048 x 16B = 32KB
        const float* src = g_M + idx*4;
        unsigned dst = (unsigned)__cvta_generic_to_shared(smem + idx*16);
        asm volatile("cp.async.ca.shared.global [%0], [%1], 16;" :: "r"(dst), "l"(src));
    }
    asm volatile("cp.async.commit_group;");

    // stage chunk ch into ring slot ch&1 (warp-private; 8 lanes per row)
    auto issue = [&](int ch){
        char* tb = wtile + (ch & 1)*STAGEB;
        #pragma unroll
        for (int i = 0; i < 32; i++){
            int idx = i*32 + lane;
            int r = idx >> 3, c = idx & 7;
            const float* src = xb + (size_t)r*D_ + ch*DC + c*4;
            unsigned dst = (unsigned)__cvta_generic_to_shared(tb + r*ROWB + c*16);
            asm volatile("cp.async.cg.shared.global [%0], [%1], 16;" :: "r"(dst), "l"(src));
        }
        asm volatile("cp.async.commit_group;");
    };

    issue(0); issue(1);
    asm volatile("cp.async.wait_group 2;");    // M group complete
    __syncthreads();                           // M visible to all warps

    u64 acc[4][8];
    #pragma unroll
    for (int g = 0; g < 4; g++)
        #pragma unroll
        for (int e = 0; e < 8; e++) acc[g][e] = 0ULL;

    for (int ch = 0; ch < NCH; ch++){
        // chunk ch ready? pending = {ch, ch+1} -> wait 1; last iter wait 0
        if (ch + 1 < NCH) asm volatile("cp.async.wait_group 1;");
        else              asm volatile("cp.async.wait_group 0;");
        __syncwarp();

        const char* tb = wtile + (ch & 1)*STAGEB;
        const char* mrow = smem + ch*128;      // + e*4096 + dp2*16
        #pragma unroll
        for (int dp2 = 0; dp2 < 8; dp2++){
            U4 xv[4];
            #pragma unroll
            for (int g = 0; g < 4; g++)
                xv[g].v = *(const uint4*)(tb + (g*32 + lane)*ROWB + dp2*16);
            #pragma unroll
            for (int e = 0; e < 8; e++){
                U4 mv; mv.v = *(const uint4*)(mrow + e*4096 + dp2*16);  // broadcast
                #pragma unroll
                for (int g = 0; g < 4; g++){
                    ffma2(acc[g][e], xv[g].u[0], mv.u[0]);
                    ffma2(acc[g][e], xv[g].u[1], mv.u[1]);
                }
            }
        }

        __syncwarp();      // all lanes done reading slot ch&1 before re-staging it
        if (ch + 2 < NCH) issue(ch + 2);
    }

    // ---- per-lane epilogue: 4 complete softmaxes ----
    float creg[8];
    #pragma unroll
    for (int e = 0; e < 8; e++) creg[e] = __ldg(&g_c[e]);

    float pw[8] = {0.f,0.f,0.f,0.f,0.f,0.f,0.f,0.f};
    float pa = 0.f;
    #pragma unroll
    for (int g = 0; g < 4; g++){
        float s[8];
        #pragma unroll
        for (int e = 0; e < 8; e++){
            float2 p = unpack2(acc[g][e]);
            s[e] = (p.x + p.y + creg[e]) * SCALE;
        }
        float mx = s[0];
        #pragma unroll
        for (int e = 1; e < 8; e++) mx = fmaxf(mx, s[e]);
        float wv[8], sum = 0.f;
        #pragma unroll
        for (int e = 0; e < 8; e++){ wv[e] = __expf(s[e] - mx); sum += wv[e]; }
        float inv = 1.0f / sum;
        #pragma unroll
        for (int e = 0; e < 8; e++){
            wv[e] *= inv;
            pa += wv[e] * __logf(wv[e] + 1e-9f);
            pw[e] += wv[e];
        }
    }

    // warp butterfly, then combine 4 warps via smem
    #pragma unroll
    for (int off = 16; off > 0; off >>= 1){
        #pragma unroll
        for (int e = 0; e < 8; e++) pw[e] += __shfl_xor_sync(0xffffffffu, pw[e], off);
        pa += __shfl_xor_sync(0xffffffffu, pa, off);
    }
    __shared__ float sRed[4][9];
    if (lane == 0){
        #pragma unroll
        for (int e = 0; e < 8; e++) sRed[w][e] = pw[e];
        sRed[w][8] = pa;
    }
    __syncthreads();
    if (tid < 9){
        float t = sRed[0][tid] + sRed[1][tid] + sRed[2][tid] + sRed[3][tid];
        if (tid < 8) g_pws[blk*8 + tid] = t;
        else         g_paux[blk]        = t;
    }
}

// ================= K3: per-batch top-2, mask2d, indices, router loss (512 thr) =================
__global__ void __launch_bounds__(512) k3(float* __restrict__ out, int out_size){
    __shared__ float ssc[64][9];
    __shared__ float sm2[64][8];
    __shared__ float sauxw[16];
    __shared__ float scnt[8];
    int tid = threadIdx.x;
    int lane = tid & 31, warp = tid >> 5;

    // aux reduction over 128 block partials
    float a = (tid < NB2) ? g_paux[tid] : 0.f;
    #pragma unroll
    for (int off = 16; off > 0; off >>= 1)
        a += __shfl_xor_sync(0xffffffffu, a, off);
    if (lane == 0) sauxw[warp] = a;

    // per-(b,e) score: 2 independent coalesced loads
    {
        int b = tid >> 3, e = tid & 7;
        float sc = g_pws[(b*2+0)*8 + e] + g_pws[(b*2+1)*8 + e];
        ssc[b][e] = sc;
    }
    __syncthreads();

    if (tid < 64){
        int b = tid;
        float sc[8];
        #pragma unroll
        for (int e = 0; e < 8; e++) sc[e] = ssc[b][e];
        // top-2, ties -> lowest index (matches jax.lax.top_k)
        int i1 = 0; float v1 = sc[0];
        #pragma unroll
        for (int e = 1; e < 8; e++) if (sc[e] > v1){ v1 = sc[e]; i1 = e; }
        int i2 = -1; float v2 = -3.0e38f;
        #pragma unroll
        for (int e = 0; e < 8; e++) if (e != i1 && sc[e] > v2){ v2 = sc[e]; i2 = e; }
        #pragma unroll
        for (int e = 0; e < 8; e++){
            float mv = (e == i1 || e == i2) ? 1.f : 0.f;
            sm2[b][e] = mv;
            g_m2d[b*8 + e] = mv;
        }
        if (out_size > IDX_OFF + b*2 + 1){
            out[IDX_OFF + b*2 + 0] = (float)i1;
            out[IDX_OFF + b*2 + 1] = (float)i2;
        }
    }
    __syncthreads();

    if (tid < 8){
        float c = 0.f;
        #pragma unroll
        for (int b = 0; b < 64; b++) c += sm2[b][tid];
        scnt[tid] = c;
    }
    __syncthreads();

    if (tid == 0){
        float auxtot = 0.f;
        #pragma unroll
        for (int wp = 0; wp < 16; wp++) auxtot += sauxw[wp];
        float kl = 0.f;
        const float ip = 0.125f;
        const float lip = logf(0.125f);
        #pragma unroll
        for (int e = 0; e < 8; e++){
            float usage = scnt[e] * (1.0f/64.0f);   // mask2d.sum(0) * S/(B*S)
            kl += ip * (lip - logf(usage));
        }
        kl *= 0.125f;                               // batchmean over E
        float auxm = auxtot * (1.0f / (float)(B_*S_*E_));
        if (out_size > LOSS_OFF)
            out[LOSS_OFF] = 1e-3f*kl + 1e-3f*auxm;
    }
}

// ================= K4: broadcast mask2d -> mask[B,S,E] =================
__global__ void __launch_bounds__(256) k4(float* __restrict__ out){
    int t = blockIdx.x*256 + threadIdx.x;   // 0..65535 (b,s) pairs
    int b = t >> 10;
    const float4* m = (const float4*)g_m2d;
    float4 a0 = __ldg(&m[b*2 + 0]);
    float4 a1 = __ldg(&m[b*2 + 1]);
    float4* o = (float4*)out;
    o[t*2 + 0] = a0;
    o[t*2 + 1] = a1;
}

extern "C" void kernel_launch(void* const* d_in, const int* in_sizes, int n_in,
                              void* d_out, int out_size){
    (void)in_sizes; (void)n_in;
    const float* x   = (const float*)d_in[0];
    const float* Wq  = (const float*)d_in[1];
    const float* bq  = (const float*)d_in[2];
    const float* key = (const float*)d_in[3];
    float* out = (float*)d_out;

    cudaFuncSetAttribute(k2, cudaFuncAttributeMaxDynamicSharedMemorySize, SMEMSZ);

    k1 <<<128,  256>>>(Wq, key);
    k1b<<<32,   256>>>(key, bq);
    k2 <<<NB2,  128, SMEMSZ>>>(x);
    k3 <<<1,    512>>>(out, out_size);
    k4 <<<256,  256>>>(out);
}